// round 12
// baseline (speedup 1.0000x reference)
#include <cuda_runtime.h>
#include <cuda_fp16.h>

#define N_NODES 8192
#define DIN 128
#define DOUT 128
#define E_EDGES 262144
#define MWORDS 256          // 8192 bits / 32 per adjacency row
#define MAXD 128            // max unique out-degree (Poisson(32): P(>96) ~ 1e-11)
#define ROWB 256            // bytes per g_feat_h row (128 fp16)
#define ZERO_OFF (N_NODES * ROWB)   // byte offset of the permanent zero row

// ---- scratch (device globals; zero-initialized at module load).
// INVARIANT: g_mask / g_cnt / g_deg are all-zero at entry AND exit of every
// kernel_launch call (k_agg restores them), so no per-call memset is needed.
__device__ int      g_deg[N_NODES];
__device__ int      g_cnt[N_NODES];
__device__ unsigned g_mask[N_NODES * MWORDS];      // dedup bitmask (sparse-touched)
__device__ int      g_nbr[N_NODES * MAXD];         // byte offsets (c*256) of unique nbrs
__device__ __half   g_feat_h[(N_NODES + 1) * DOUT];// fp16 g[j]=dinv[j]*(x W^T+b); row N = 0
__device__ float    g_wt[DIN * DOUT];              // W^T: g_wt[k*128+c] = W[c][k]

// packed f32x2 FMA helpers (FFMA2 SASS — ptxas never auto-fuses from C++)
__device__ __forceinline__ void ffma2(unsigned long long& acc,
                                      unsigned long long a, unsigned long long b) {
    asm("fma.rn.f32x2 %0, %1, %2, %0;" : "+l"(acc) : "l"(a), "l"(b));
}
__device__ __forceinline__ unsigned long long dup2(float v) {
    unsigned long long r;
    asm("mov.b64 %0, {%1, %1};" : "=l"(r) : "f"(v));
    return r;
}
__device__ __forceinline__ float2 unpack2(unsigned long long v) {
    float2 f;
    asm("mov.b64 {%0, %1}, %2;" : "=f"(f.x), "=f"(f.y) : "l"(v));
    return f;
}

__device__ __forceinline__ float dinv_of(int d) {
    return (d > 0) ? rsqrtf((float)d) : 0.0f;
}

// -------------------------------------------------- edge pass (+ fused W^T)
// deg counts ALL edges (multiplicity, matches .at[row].add); bitmask dedups
// adjacency (matches .at[row,col].set). First setter appends the neighbor's
// BYTE OFFSET into g_feat_h (c*256). First 64 blocks also transpose W.
__global__ void k_edges(const int* __restrict__ ei, const float* __restrict__ W) {
    int t = blockIdx.x * blockDim.x + threadIdx.x;
    if (t < DIN * DOUT) {                          // W^T (coalesced writes)
        int k = t / DOUT, c = t % DOUT;
        g_wt[k * DOUT + c] = W[c * DIN + k];
    }
    if (t >= E_EDGES) return;
    int r = ei[t];
    int c = ei[E_EDGES + t];
    atomicAdd(&g_deg[r], 1);                       // no return use -> REDG
    unsigned m = 1u << (c & 31);
    unsigned old = atomicOr(&g_mask[r * MWORDS + (c >> 5)], m);
    if (!(old & m)) {
        int p = atomicAdd(&g_cnt[r], 1);
        if (p < MAXD) g_nbr[r * MAXD + p] = c << 8;   // c * 256 bytes
    }
}

// ---------------------------------------------------------------- fused GEMM
// g_feat_h[i] = fp16( dinv[i] * (x[i] @ W^T + b) ). 64 rows/block, 256 thr.
// warp w owns rows w*8..w*8+7; lane l owns cols 4l..4l+3 as two f32x2 pairs.
#define GROWS 64
__global__ __launch_bounds__(256) void k_gemm(const float* __restrict__ x,
                                              const float* __restrict__ bias) {
    __shared__ float xs[GROWS][DIN];   // 32 KB
    const int row0 = blockIdx.x * GROWS;
    const int t = threadIdx.x;

    const float4* xin = (const float4*)(x + row0 * DIN);
    float4* xs4 = (float4*)&xs[0][0];
#pragma unroll
    for (int i = 0; i < 8; i++) xs4[t + 256 * i] = xin[t + 256 * i];
    __syncthreads();

    const int w = t >> 5, l = t & 31;
    const int r0 = w * 8;
    const int c0 = l * 4;

    unsigned long long acc[8][2];
#pragma unroll
    for (int r = 0; r < 8; r++) { acc[r][0] = 0ull; acc[r][1] = 0ull; }

#pragma unroll 2
    for (int k = 0; k < DIN; k += 4) {
        ulonglong2 wv[4];
#pragma unroll
        for (int j = 0; j < 4; j++)
            wv[j] = *(const ulonglong2*)&g_wt[(k + j) * DOUT + c0];
#pragma unroll
        for (int r = 0; r < 8; r++) {
            float4 xv = *(const float4*)&xs[r0 + r][k];   // broadcast LDS.128
            unsigned long long x2;
            x2 = dup2(xv.x); ffma2(acc[r][0], x2, wv[0].x); ffma2(acc[r][1], x2, wv[0].y);
            x2 = dup2(xv.y); ffma2(acc[r][0], x2, wv[1].x); ffma2(acc[r][1], x2, wv[1].y);
            x2 = dup2(xv.z); ffma2(acc[r][0], x2, wv[2].x); ffma2(acc[r][1], x2, wv[2].y);
            x2 = dup2(xv.w); ffma2(acc[r][0], x2, wv[3].x); ffma2(acc[r][1], x2, wv[3].y);
        }
    }

    float4 bv = *(const float4*)&bias[c0];
#pragma unroll
    for (int r = 0; r < 8; r++) {
        int row = row0 + r0 + r;
        float dv = dinv_of(g_deg[row]);
        float2 lo = unpack2(acc[r][0]);
        float2 hi = unpack2(acc[r][1]);
        __half2 h01 = __floats2half2_rn(dv * (lo.x + bv.x), dv * (lo.y + bv.y));
        __half2 h23 = __floats2half2_rn(dv * (hi.x + bv.z), dv * (hi.y + bv.w));
        uint2 pk;
        pk.x = *reinterpret_cast<unsigned*>(&h01);
        pk.y = *reinterpret_cast<unsigned*>(&h23);
        *reinterpret_cast<uint2*>((char*)g_feat_h + row * ROWB + c0 * 2) = pk;
    }
}

// ---------------------------------------------------------------- aggregation
// Warp per node. Half-warp per neighbor: lane l reads the 16 bytes
// (features (l&15)*8 .. +7, 8 fp16) of neighbor nb[p + (l>>4)] in one LDG.128.
// Software-pipelined: two 4-load groups issued back-to-back -> 8 LDG.128 in
// flight per lane. fp32 accumulation; cross-half-warp fold via shfl_xor(16).
// Scratch-invariant restore stores are issued BEFORE the gather so they drain
// in the shadow of the loads.
__device__ __forceinline__ void agg_load(uint4 v[4], const char* base,
                                         const int* nbw, int p, int half) {
#pragma unroll
    for (int u = 0; u < 4; u++)
        v[u] = *(const uint4*)(base + nbw[p + 2 * u + half]);
}
__device__ __forceinline__ void agg_acc(float2 a[4], const uint4 v[4]) {
#pragma unroll
    for (int u = 0; u < 4; u++) {
        const __half2* h = reinterpret_cast<const __half2*>(&v[u]);
#pragma unroll
        for (int j = 0; j < 4; j++) {
            float2 f = __half22float2(h[j]);
            a[j].x += f.x;
            a[j].y += f.y;
        }
    }
}

__global__ __launch_bounds__(256) void k_agg(float* __restrict__ out) {
    __shared__ int nb[8][MAXD];
    const int w = threadIdx.x >> 5, l = threadIdx.x & 31;
    const int i = blockIdx.x * 8 + w;
    const int half = l >> 4;
    const int fl = l & 15;

    int cnt = g_cnt[i];
    if (cnt > MAXD) cnt = MAXD;
    int deg = g_deg[i];

    int* nbw = nb[w];
    for (int p = l; p < cnt; p += 32) nbw[p] = g_nbr[i * MAXD + p];
    int cnt_pad = (cnt + 7) & ~7;
    for (int p = cnt + l; p < cnt_pad; p += 32) nbw[p] = ZERO_OFF;  // pad -> zero row
    __syncwarp();

    // restore scratch invariant early (issue-only stores; drain under gather)
    for (int p = l; p < cnt; p += 32)
        g_mask[i * MWORDS + (nbw[p] >> 13)] = 0;   // (c*256)>>8>>5
    if (l == 0) { g_cnt[i] = 0; g_deg[i] = 0; }

    const char* base = (const char*)g_feat_h + fl * 16;
    float2 a[4];
#pragma unroll
    for (int j = 0; j < 4; j++) a[j] = make_float2(0.f, 0.f);

    uint4 va[4], vb[4];
    int p = 0;
    for (; p + 16 <= cnt_pad; p += 16) {   // 8 LDG.128 in flight per lane
        agg_load(va, base, nbw, p, half);
        agg_load(vb, base, nbw, p + 8, half);
        agg_acc(a, va);
        agg_acc(a, vb);
    }
    if (p < cnt_pad) {                     // one trailing 8-group
        agg_load(va, base, nbw, p, half);
        agg_acc(a, va);
    }

    float r[8];
#pragma unroll
    for (int j = 0; j < 4; j++) { r[2 * j] = a[j].x; r[2 * j + 1] = a[j].y; }
#pragma unroll
    for (int k = 0; k < 8; k++)                      // fold the two half-warps
        r[k] += __shfl_xor_sync(0xffffffffu, r[k], 16);

    float dv = dinv_of(deg);
    if (l < 16) {
        float4 o0, o1;
        o0.x = dv * r[0]; o0.y = dv * r[1]; o0.z = dv * r[2]; o0.w = dv * r[3];
        o1.x = dv * r[4]; o1.y = dv * r[5]; o1.z = dv * r[6]; o1.w = dv * r[7];
        o0.x = o0.x > 0.f ? o0.x : 0.f;  o0.y = o0.y > 0.f ? o0.y : 0.f;
        o0.z = o0.z > 0.f ? o0.z : 0.f;  o0.w = o0.w > 0.f ? o0.w : 0.f;
        o1.x = o1.x > 0.f ? o1.x : 0.f;  o1.y = o1.y > 0.f ? o1.y : 0.f;
        o1.z = o1.z > 0.f ? o1.z : 0.f;  o1.w = o1.w > 0.f ? o1.w : 0.f;
        float4* dst = (float4*)&out[i * DOUT + fl * 8];
        dst[0] = o0;
        dst[1] = o1;
    }
}

// ---------------------------------------------------------------- launch
extern "C" void kernel_launch(void* const* d_in, const int* in_sizes, int n_in,
                              void* d_out, int out_size) {
    const float* x    = (const float*)d_in[0];   // [8192,128] f32
    const int*   ei   = (const int*)d_in[1];     // [2,262144] i32
    const float* W    = (const float*)d_in[2];   // [128,128]  f32
    const float* bias = (const float*)d_in[3];   // [128]      f32
    float* out = (float*)d_out;                  // [8192,128] f32

    k_edges<<<E_EDGES / 256, 256>>>(ei, W);
    k_gemm <<<N_NODES / GROWS, 256>>>(x, bias);
    k_agg  <<<N_NODES / 8, 256>>>(out);
}